// round 15
// baseline (speedup 1.0000x reference)
#include <cuda_runtime.h>
#include <cstdint>

#define Bdim 32
#define Kdim 17
#define Hdim 160
#define Wdim 160
#define HW   (Hdim*Wdim)
#define NG   (HW/4)
#define Pn   30
#define Sn   10
#define Ln   19
#define NCH  (Bdim*Kdim)
#define T1   320
#define NSTRIP 20
#define SPX   8
#define RPB   10
#define CAP1  4096
#define T2   512
#define NBINS 1024
#define SCAP  256
#define NEGF  (-1.0e30f)
// stage2 band pipeline
#define BANDROWS 20
#define BANDSZ   (BANDROWS*Wdim)    // 3200 floats = 12.8KB
#define NBAND2   8
#define NCHUNK   16                  // 8 x-bands + 8 y-bands
#define RB       8                   // ring depth (8 * 12.8KB = 100KB)

__constant__ int c_skel_a[Ln] = {15,13,16,14,11, 5, 6, 5, 5, 6, 7, 8, 1, 0, 0, 1, 2, 3, 4};
__constant__ int c_skel_b[Ln] = {13,11,14,12,12,11,12, 6, 7, 8, 9,10, 2, 1, 2, 3, 4, 5, 6};

// ---------------- cp.async helpers ----------------
__device__ __forceinline__ void cp16(void* s, const void* g) {
    unsigned sa = (unsigned)__cvta_generic_to_shared(s);
    asm volatile("cp.async.cg.shared.global [%0], [%1], 16;\n" :: "r"(sa), "l"(g));
}
__device__ __forceinline__ void cp_commit() { asm volatile("cp.async.commit_group;\n"); }
template <int N>
__device__ __forceinline__ void cp_wait() { asm volatile("cp.async.wait_group %0;\n" :: "n"(N)); }

__device__ __forceinline__ void wait_n(int n) {
    switch (n) {
        case 0: cp_wait<0>(); break;
        case 1: cp_wait<1>(); break;
        case 2: cp_wait<2>(); break;
        case 3: cp_wait<3>(); break;
        case 4: cp_wait<4>(); break;
        case 5: cp_wait<5>(); break;
        case 6: cp_wait<6>(); break;
        default: cp_wait<7>(); break;
    }
}

// monotone bin: v = h^9 (uniform-izes max-of-9 peak-score distribution)
__device__ __forceinline__ int bin_of(float h) {
    float h2 = h * h;
    float h4 = h2 * h2;
    float v  = h4 * h4 * h;
    int b = (int)(v * (float)NBINS);
    return b < 0 ? 0 : (b > NBINS - 1 ? NBINS - 1 : b);
}

__device__ __forceinline__ float max3(float a, float b, float c) {
    return fmaxf(fmaxf(a, b), c);
}

// load one row of an 8px strip: 2 contiguous float4 + 2 edge scalars.
__device__ __forceinline__ void loadrow8(const float* __restrict__ hp,
                                         int y, int x0, bool lf, bool rt,
                                         float rm[8], float px[8])
{
    if (y < 0 || y >= Hdim) {
        #pragma unroll
        for (int j = 0; j < SPX; ++j) { rm[j] = NEGF; px[j] = NEGF; }
        return;
    }
    const float4* p4 = (const float4*)(hp + y * Wdim + x0);
    float4 A = __ldg(p4);
    float4 B = __ldg(p4 + 1);
    float w[SPX + 2];
    w[0] = lf ? __ldg(hp + y * Wdim + x0 - 1) : NEGF;
    w[1] = A.x; w[2] = A.y; w[3] = A.z; w[4] = A.w;
    w[5] = B.x; w[6] = B.y; w[7] = B.z; w[8] = B.w;
    w[9] = rt ? __ldg(hp + y * Wdim + x0 + SPX) : NEGF;
    #pragma unroll
    for (int j = 0; j < SPX; ++j) {
        px[j] = w[j + 1];
        rm[j] = max3(w[j], w[j + 1], w[j + 2]);
    }
}

// ---------------------------------------------------------------------------
// Stage 1 (R10, byte-identical): strip sweep + smem list + histogram select.
// ---------------------------------------------------------------------------
__global__ void __launch_bounds__(T1) stage1_kernel(const float* __restrict__ heat,
                                                    float* __restrict__ out_peaks)
{
    if (threadIdx.x == 0) cudaTriggerProgrammaticLaunchCompletion();

    __shared__ unsigned long long list[CAP1];
    __shared__ unsigned hist[NBINS];
    __shared__ unsigned long long surv[SCAP];
    __shared__ unsigned long long s_top[Pn];
    __shared__ int s_cnt, s_sc, s_cut;

    const int ch = blockIdx.x;
    const float* hp = heat + (size_t)ch * HW;
    const int tid = threadIdx.x;
    const int lane = tid & 31;

    for (int i = tid; i < NBINS; i += T1) hist[i] = 0;
    if (tid == 0) { s_cnt = 0; s_sc = 0; s_cut = 0; }
    __syncthreads();

    const int strip = tid % NSTRIP;
    const int band  = tid / NSTRIP;
    const int x0 = strip * SPX;
    const int y0 = band * RPB;
    const bool lf = (strip > 0);
    const bool rt = (strip < NSTRIP - 1);

    float rmU[SPX], rmC[SPX], rmD[SPX];
    float C8[SPX], D8[SPX];

    loadrow8(hp, y0 - 1, x0, lf, rt, rmU, D8);
    loadrow8(hp, y0,     x0, lf, rt, rmC, C8);

    #pragma unroll 2
    for (int r = 0; r < RPB; ++r) {
        const int y = y0 + r;
        loadrow8(hp, y + 1, x0, lf, rt, rmD, D8);
        #pragma unroll
        for (int j = 0; j < SPX; ++j) {
            float h = C8[j];
            if (h > 0.1f && h >= rmU[j] && h >= rmC[j] && h >= rmD[j]) {
                int pos = atomicAdd(&s_cnt, 1);
                if (pos < CAP1) {
                    unsigned idx = (unsigned)(y * Wdim + x0 + j);
                    list[pos] = ((unsigned long long)__float_as_uint(h) << 32) |
                                (unsigned long long)(0xFFFFFFFFu - idx);
                }
            }
        }
        #pragma unroll
        for (int j = 0; j < SPX; ++j) {
            rmU[j] = rmC[j]; rmC[j] = rmD[j]; C8[j] = D8[j];
        }
    }
    __syncthreads();

    const int m = (s_cnt < CAP1) ? s_cnt : CAP1;

    for (int i = tid; i < m; i += T1) {
        float h = __uint_as_float((unsigned)(list[i] >> 32));
        atomicAdd(&hist[bin_of(h)], 1u);
    }
    __syncthreads();

    if (tid < 32) {
        int acc = 0, cut = 0;
        for (int base = NBINS - 32; base >= 0; base -= 32) {
            int s = (int)hist[base + lane];
            #pragma unroll
            for (int off = 1; off < 32; off <<= 1) {
                int t = __shfl_down_sync(0xffffffffu, s, off);
                if (lane + off < 32) s += t;
            }
            int chunk_total = __shfl_sync(0xffffffffu, s, 0);
            if (acc + chunk_total >= Pn) {
                unsigned msk = __ballot_sync(0xffffffffu, acc + s >= Pn);
                cut = base + (31 - __clz(msk));
                break;
            }
            acc += chunk_total;
        }
        if (lane == 0) s_cut = cut;
    }
    __syncthreads();

    const int cut = s_cut;
    for (int i = tid; i < m; i += T1) {
        unsigned long long key = list[i];
        if (bin_of(__uint_as_float((unsigned)(key >> 32))) >= cut) {
            int pos = atomicAdd(&s_sc, 1);
            if (pos < SCAP) surv[pos] = key;
        }
    }
    __syncthreads();

    if (tid < 32) {
        const int n = (s_sc < SCAP) ? s_sc : SCAP;
        for (int p = 0; p < Pn; ++p) {
            unsigned long long best = 0ull;
            int bpos = -1;
            for (int i = lane; i < n; i += 32) {
                unsigned long long c = surv[i];
                if (c > best) { best = c; bpos = i; }
            }
            #pragma unroll
            for (int off = 16; off > 0; off >>= 1) {
                unsigned long long ob = __shfl_down_sync(0xffffffffu, best, off);
                int op = __shfl_down_sync(0xffffffffu, bpos, off);
                if (ob > best) { best = ob; bpos = op; }
            }
            best = __shfl_sync(0xffffffffu, best, 0);
            bpos = __shfl_sync(0xffffffffu, bpos, 0);
            if (lane == 0) {
                s_top[p] = best;
                if (bpos >= 0) surv[bpos] = 0ull;
            }
            __syncwarp();
        }

        if (lane < Pn) {
            unsigned long long key = s_top[lane];
            float px = 0.f, py = 0.f, sc = 0.f;
            if (key != 0ull) {
                unsigned idx = 0xFFFFFFFFu - (unsigned)(key & 0xFFFFFFFFu);
                float h = __uint_as_float((unsigned)(key >> 32));
                int y = idx / Wdim;
                int x = idx - y * Wdim;
                float dx = 0.f, dy = 0.f;
                if (y > 0 && y < Hdim - 1 && x > 0 && x < Wdim - 1) {
                    float r = __ldg(hp + idx + 1),    l = __ldg(hp + idx - 1);
                    float d = __ldg(hp + idx + Wdim), u = __ldg(hp + idx - Wdim);
                    float dxr = 0.5f * (r - l);
                    float dxx = (r + l) - 2.0f * h;
                    dx = (fabsf(dxx) > 1e-6f) ? (dxr / (-dxx)) : dxr;
                    float dyr = 0.5f * (d - u);
                    float dyy = (d + u) - 2.0f * h;
                    dy = (fabsf(dyy) > 1e-6f) ? (dyr / (-dyy)) : dyr;
                }
                px = (float)x + dx;
                py = (float)y + dy;
                sc = h;
            }
            float* o = out_peaks + ((size_t)ch * Pn + lane) * 3;
            o[0] = px; o[1] = py; o[2] = sc;
        }
    }
}

// ---------------------------------------------------------------------------
// Stage 2: per-(b,l) limb, band-pipelined.  8-deep ring of 12.8KB band
// buffers; 16 chunks (8 x-bands, 8 y-bands).  DRAM stays continuously fed.
// Arithmetic identical to R10 (per-sample products, s-ordered final sum).
// ---------------------------------------------------------------------------
__global__ void __launch_bounds__(T2, 2) stage2_kernel(const float* __restrict__ paf,
                                                       const float* __restrict__ peaks,
                                                       float* __restrict__ conn)
{
    extern __shared__ float ring[];              // RB * BANDSZ floats

    __shared__ float sax[Pn], say[Pn], sas[Pn];
    __shared__ float sbx[Pn], sby[Pn], sbs[Pn];

    const int bl = blockIdx.x;
    const int b = bl / Ln;
    const int l = bl - b * Ln;
    const int tid = threadIdx.x;

    const float* base_x = paf + ((size_t)b * 38 + 2 * l) * HW;
    const float* base_y = base_x + HW;

    // prologue: issue all 8 x-band chunks (102KB in flight, overlaps stage1)
    #pragma unroll
    for (int c = 0; c < RB; ++c) {
        const float4* src = (const float4*)(base_x + c * BANDSZ);
        float4* dst = (float4*)(ring + c * BANDSZ);
        for (int i = tid; i < BANDSZ / 4; i += T2) cp16(dst + i, src + i);
        cp_commit();
    }

    cudaGridDependencySynchronize();             // peaks valid from here

    const int ja = c_skel_a[l];
    const int jb = c_skel_b[l];
    if (tid < Pn) {
        const float* pa = peaks + ((size_t)(b * Kdim + ja) * Pn + tid) * 3;
        sax[tid] = pa[0]; say[tid] = pa[1]; sas[tid] = pa[2];
    } else if (tid >= 32 && tid < 32 + Pn) {
        int j = tid - 32;
        const float* pb = peaks + ((size_t)(b * Kdim + jb) * Pn + j) * 3;
        sbx[j] = pb[0]; sby[j] = pb[1]; sbs[j] = pb[2];
    }
    __syncthreads();

    // pair geometry + sample indices (independent of PAF data)
    int   lin[2][Sn];
    float xp [2][Sn];
    float vxv[2], vyv[2], halfs[2];
    bool  pv[2];
    const float step = 1.0f / 9.0f;

    #pragma unroll
    for (int q = 0; q < 2; ++q) {
        int pr = tid + q * T2;
        bool act = (pr < Pn * Pn);
        int i = act ? (pr / Pn) : 0;
        int j = act ? (pr - i * Pn) : 0;
        float ax = sax[i], ay = say[i], sa = sas[i];
        float bx = sbx[j], by = sby[j], sb = sbs[j];
        bool valid = act && (sa > 0.1f) && (sb > 0.1f);
        pv[q] = valid;
        halfs[q] = 0.5f * (sa + sb);
        float dxl = bx - ax;
        float dyl = by - ay;
        float norm = sqrtf(__fadd_rn(__fmul_rn(dxl, dxl), __fmul_rn(dyl, dyl))) + 1e-8f;
        vxv[q] = dxl / norm;
        vyv[q] = dyl / norm;
        #pragma unroll
        for (int s = 0; s < Sn; ++s) {
            float t = (float)s * step;
            // no-FMA: a ulp flip at a .5 boundary changes the gathered cell
            float xs = __fadd_rn(ax, __fmul_rn(t, dxl));
            float ys = __fadd_rn(ay, __fmul_rn(t, dyl));
            float fx = fminf(fmaxf(rintf(xs), 0.0f), (float)(Wdim - 1));
            float fy = fminf(fmaxf(rintf(ys), 0.0f), (float)(Hdim - 1));
            lin[q][s] = valid ? ((int)fy * Wdim + (int)fx) : 0;
        }
    }

    // chunk loop: 0..7 = x bands, 8..15 = y bands; ring reuse after 8
    #pragma unroll
    for (int c = 0; c < NCHUNK; ++c) {
        wait_n((c <= 8) ? (RB - 1) : (NCHUNK - 1 - c));
        __syncthreads();

        const int band = (c < NBAND2) ? c : c - NBAND2;
        const float* bb = ring + (c % RB) * BANDSZ;
        const int lo = band * BANDSZ;
        const int hi = lo + BANDSZ;

        if (c < NBAND2) {
            #pragma unroll
            for (int q = 0; q < 2; ++q)
                #pragma unroll
                for (int s = 0; s < Sn; ++s) {
                    int li = lin[q][s];
                    if (li >= lo && li < hi)
                        xp[q][s] = __fmul_rn(bb[li - lo], vxv[q]);
                }
        } else {
            #pragma unroll
            for (int q = 0; q < 2; ++q)
                #pragma unroll
                for (int s = 0; s < Sn; ++s) {
                    int li = lin[q][s];
                    if (li >= lo && li < hi)
                        xp[q][s] = __fadd_rn(xp[q][s], __fmul_rn(bb[li - lo], vyv[q]));
                }
        }
        __syncthreads();

        if (c + RB < NCHUNK) {                   // refill freed buffer: y band
            const int yb = c + RB - NBAND2;      // c .. (y band index = c)
            const float4* src = (const float4*)(base_y + yb * BANDSZ);
            float4* dst = (float4*)(ring + ((c + RB) % RB) * BANDSZ);
            for (int i = tid; i < BANDSZ / 4; i += T2) cp16(dst + i, src + i);
            cp_commit();
        }
    }

    // epilogue: s-ordered sum (identical fp chain to R10)
    float* co = conn + (size_t)bl * Pn * Pn;
    #pragma unroll
    for (int q = 0; q < 2; ++q) {
        int pr = tid + q * T2;
        bool act = (pr < Pn * Pn);
        float sum = 0.0f;
        int c = 0;
        #pragma unroll
        for (int s = 0; s < Sn; ++s) {
            float v = xp[q][s];
            sum = __fadd_rn(sum, v);
            c += (v > 0.05f) ? 1 : 0;
        }
        float outv = 0.0f;
        if (pv[q]) {
            float mean = sum / 10.0f;
            float ratio = (float)c / 10.0f;
            if (mean > 0.0f && ratio > 0.8f)
                outv = mean + halfs[q];
        }
        if (act) co[pr] = outv;
    }
}

// ---------------------------------------------------------------------------
extern "C" void kernel_launch(void* const* d_in, const int* in_sizes, int n_in,
                              void* d_out, int out_size)
{
    const float* heat = (const float*)d_in[0];
    const float* paf  = (const float*)d_in[1];
    float* out   = (float*)d_out;
    float* peaks = out;                                  // B*K*P*3 = 48960
    float* conn  = out + (size_t)Bdim * Kdim * Pn * 3;   // B*L*P*P = 547200

    const int smem2 = RB * BANDSZ * 4;                   // 102400 -> 2 blocks/SM
    cudaFuncSetAttribute(stage2_kernel, cudaFuncAttributeMaxDynamicSharedMemorySize, smem2);

    stage1_kernel<<<NCH, T1>>>(heat, peaks);

    cudaLaunchConfig_t cfg = {};
    cfg.gridDim = dim3(Bdim * Ln);
    cfg.blockDim = dim3(T2);
    cfg.dynamicSmemBytes = smem2;
    cfg.stream = 0;
    cudaLaunchAttribute attrs[1];
    attrs[0].id = cudaLaunchAttributeProgrammaticStreamSerialization;
    attrs[0].val.programmaticStreamSerializationAllowed = 1;
    cfg.attrs = attrs;
    cfg.numAttrs = 1;
    cudaLaunchKernelEx(&cfg, stage2_kernel, paf, (const float*)peaks, conn);
}

// round 16
// speedup vs baseline: 1.4110x; 1.4110x over previous
#include <cuda_runtime.h>
#include <cstdint>

#define Bdim 32
#define Kdim 17
#define Hdim 160
#define Wdim 160
#define HW   (Hdim*Wdim)
#define NG   (HW/4)
#define Pn   30
#define Sn   10
#define Ln   19
#define NCH  (Bdim*Kdim)
#define T1   320
#define NSTRIP 20
#define SPX   8
#define RPB   10
#define CAP1  4096
#define T2   512
#define NBINS 1024
#define SCAP  256
#define NEGF  (-1.0e30f)

__constant__ int c_skel_a[Ln] = {15,13,16,14,11, 5, 6, 5, 5, 6, 7, 8, 1, 0, 0, 1, 2, 3, 4};
__constant__ int c_skel_b[Ln] = {13,11,14,12,12,11,12, 6, 7, 8, 9,10, 2, 1, 2, 3, 4, 5, 6};

// ---------------- cp.async helpers ----------------
__device__ __forceinline__ void cp16(void* s, const void* g) {
    unsigned sa = (unsigned)__cvta_generic_to_shared(s);
    asm volatile("cp.async.cg.shared.global [%0], [%1], 16;\n" :: "r"(sa), "l"(g));
}
__device__ __forceinline__ void cp_commit() { asm volatile("cp.async.commit_group;\n"); }
template <int N>
__device__ __forceinline__ void cp_wait() { asm volatile("cp.async.wait_group %0;\n" :: "n"(N)); }

__device__ __forceinline__ void l2_prefetch(const void* p) {
    asm volatile("prefetch.global.L2 [%0];" :: "l"(p));
}

// monotone bin: v = h^9 (uniform-izes max-of-9 peak-score distribution)
__device__ __forceinline__ int bin_of(float h) {
    float h2 = h * h;
    float h4 = h2 * h2;
    float v  = h4 * h4 * h;
    int b = (int)(v * (float)NBINS);
    return b < 0 ? 0 : (b > NBINS - 1 ? NBINS - 1 : b);
}

__device__ __forceinline__ float max3(float a, float b, float c) {
    return fmaxf(fmaxf(a, b), c);
}

// load one row of an 8px strip: 2 contiguous float4 + 2 edge scalars.
__device__ __forceinline__ void loadrow8(const float* __restrict__ hp,
                                         int y, int x0, bool lf, bool rt,
                                         float rm[8], float px[8])
{
    if (y < 0 || y >= Hdim) {
        #pragma unroll
        for (int j = 0; j < SPX; ++j) { rm[j] = NEGF; px[j] = NEGF; }
        return;
    }
    const float4* p4 = (const float4*)(hp + y * Wdim + x0);
    float4 A = __ldg(p4);
    float4 B = __ldg(p4 + 1);
    float w[SPX + 2];
    w[0] = lf ? __ldg(hp + y * Wdim + x0 - 1) : NEGF;
    w[1] = A.x; w[2] = A.y; w[3] = A.z; w[4] = A.w;
    w[5] = B.x; w[6] = B.y; w[7] = B.z; w[8] = B.w;
    w[9] = rt ? __ldg(hp + y * Wdim + x0 + SPX) : NEGF;
    #pragma unroll
    for (int j = 0; j < SPX; ++j) {
        px[j] = w[j + 1];
        rm[j] = max3(w[j], w[j + 1], w[j + 2]);
    }
}

// ---------------------------------------------------------------------------
// Stage 1 (R10, byte-identical): strip sweep + smem list + histogram select.
// ---------------------------------------------------------------------------
__global__ void __launch_bounds__(T1) stage1_kernel(const float* __restrict__ heat,
                                                    float* __restrict__ out_peaks)
{
    if (threadIdx.x == 0) cudaTriggerProgrammaticLaunchCompletion();

    __shared__ unsigned long long list[CAP1];
    __shared__ unsigned hist[NBINS];
    __shared__ unsigned long long surv[SCAP];
    __shared__ unsigned long long s_top[Pn];
    __shared__ int s_cnt, s_sc, s_cut;

    const int ch = blockIdx.x;
    const float* hp = heat + (size_t)ch * HW;
    const int tid = threadIdx.x;
    const int lane = tid & 31;

    for (int i = tid; i < NBINS; i += T1) hist[i] = 0;
    if (tid == 0) { s_cnt = 0; s_sc = 0; s_cut = 0; }
    __syncthreads();

    const int strip = tid % NSTRIP;
    const int band  = tid / NSTRIP;
    const int x0 = strip * SPX;
    const int y0 = band * RPB;
    const bool lf = (strip > 0);
    const bool rt = (strip < NSTRIP - 1);

    float rmU[SPX], rmC[SPX], rmD[SPX];
    float C8[SPX], D8[SPX];

    loadrow8(hp, y0 - 1, x0, lf, rt, rmU, D8);
    loadrow8(hp, y0,     x0, lf, rt, rmC, C8);

    #pragma unroll 2
    for (int r = 0; r < RPB; ++r) {
        const int y = y0 + r;
        loadrow8(hp, y + 1, x0, lf, rt, rmD, D8);
        #pragma unroll
        for (int j = 0; j < SPX; ++j) {
            float h = C8[j];
            if (h > 0.1f && h >= rmU[j] && h >= rmC[j] && h >= rmD[j]) {
                int pos = atomicAdd(&s_cnt, 1);
                if (pos < CAP1) {
                    unsigned idx = (unsigned)(y * Wdim + x0 + j);
                    list[pos] = ((unsigned long long)__float_as_uint(h) << 32) |
                                (unsigned long long)(0xFFFFFFFFu - idx);
                }
            }
        }
        #pragma unroll
        for (int j = 0; j < SPX; ++j) {
            rmU[j] = rmC[j]; rmC[j] = rmD[j]; C8[j] = D8[j];
        }
    }
    __syncthreads();

    const int m = (s_cnt < CAP1) ? s_cnt : CAP1;

    for (int i = tid; i < m; i += T1) {
        float h = __uint_as_float((unsigned)(list[i] >> 32));
        atomicAdd(&hist[bin_of(h)], 1u);
    }
    __syncthreads();

    if (tid < 32) {
        int acc = 0, cut = 0;
        for (int base = NBINS - 32; base >= 0; base -= 32) {
            int s = (int)hist[base + lane];
            #pragma unroll
            for (int off = 1; off < 32; off <<= 1) {
                int t = __shfl_down_sync(0xffffffffu, s, off);
                if (lane + off < 32) s += t;
            }
            int chunk_total = __shfl_sync(0xffffffffu, s, 0);
            if (acc + chunk_total >= Pn) {
                unsigned msk = __ballot_sync(0xffffffffu, acc + s >= Pn);
                cut = base + (31 - __clz(msk));
                break;
            }
            acc += chunk_total;
        }
        if (lane == 0) s_cut = cut;
    }
    __syncthreads();

    const int cut = s_cut;
    for (int i = tid; i < m; i += T1) {
        unsigned long long key = list[i];
        if (bin_of(__uint_as_float((unsigned)(key >> 32))) >= cut) {
            int pos = atomicAdd(&s_sc, 1);
            if (pos < SCAP) surv[pos] = key;
        }
    }
    __syncthreads();

    if (tid < 32) {
        const int n = (s_sc < SCAP) ? s_sc : SCAP;
        for (int p = 0; p < Pn; ++p) {
            unsigned long long best = 0ull;
            int bpos = -1;
            for (int i = lane; i < n; i += 32) {
                unsigned long long c = surv[i];
                if (c > best) { best = c; bpos = i; }
            }
            #pragma unroll
            for (int off = 16; off > 0; off >>= 1) {
                unsigned long long ob = __shfl_down_sync(0xffffffffu, best, off);
                int op = __shfl_down_sync(0xffffffffu, bpos, off);
                if (ob > best) { best = ob; bpos = op; }
            }
            best = __shfl_sync(0xffffffffu, best, 0);
            bpos = __shfl_sync(0xffffffffu, bpos, 0);
            if (lane == 0) {
                s_top[p] = best;
                if (bpos >= 0) surv[bpos] = 0ull;
            }
            __syncwarp();
        }

        if (lane < Pn) {
            unsigned long long key = s_top[lane];
            float px = 0.f, py = 0.f, sc = 0.f;
            if (key != 0ull) {
                unsigned idx = 0xFFFFFFFFu - (unsigned)(key & 0xFFFFFFFFu);
                float h = __uint_as_float((unsigned)(key >> 32));
                int y = idx / Wdim;
                int x = idx - y * Wdim;
                float dx = 0.f, dy = 0.f;
                if (y > 0 && y < Hdim - 1 && x > 0 && x < Wdim - 1) {
                    float r = __ldg(hp + idx + 1),    l = __ldg(hp + idx - 1);
                    float d = __ldg(hp + idx + Wdim), u = __ldg(hp + idx - Wdim);
                    float dxr = 0.5f * (r - l);
                    float dxx = (r + l) - 2.0f * h;
                    dx = (fabsf(dxx) > 1e-6f) ? (dxr / (-dxx)) : dxr;
                    float dyr = 0.5f * (d - u);
                    float dyy = (d + u) - 2.0f * h;
                    dy = (fabsf(dyy) > 1e-6f) ? (dyr / (-dyy)) : dyr;
                }
                px = (float)x + dx;
                py = (float)y + dy;
                sc = h;
            }
            float* o = out_peaks + ((size_t)ch * Pn + lane) * 3;
            o[0] = px; o[1] = py; o[2] = sc;
        }
    }
}

// ---------------------------------------------------------------------------
// Stage 2 (R10 structure): per-(b,l) limb, one PAF channel in smem at a time
// (100KB, 2 blocks/SM).  NEW: L2-prefetch of the y-channel issued alongside
// the x cp.async, so the later y load hits L2 instead of DRAM.
// ---------------------------------------------------------------------------
__global__ void __launch_bounds__(T2, 2) stage2_kernel(const float* __restrict__ paf,
                                                       const float* __restrict__ peaks,
                                                       float* __restrict__ conn)
{
    extern __shared__ float s2[];                // HW floats (reused x then y)

    __shared__ float sax[Pn], say[Pn], sas[Pn];
    __shared__ float sbx[Pn], sby[Pn], sbs[Pn];

    const int bl = blockIdx.x;      // b*Ln + l
    const int b = bl / Ln;
    const int l = bl - b * Ln;

    const float4* gx = (const float4*)(paf + ((size_t)b * 38 + 2 * l) * HW);
    const float4* gy = (const float4*)(paf + ((size_t)b * 38 + 2 * l + 1) * HW);

    for (int i = threadIdx.x; i < NG; i += T2)
        cp16(&((float4*)s2)[i], &gx[i]);
    cp_commit();

    // prefetch y channel to L2 (800 x 128B lines; ~1.6 instr/thread)
    {
        const char* yb = (const char*)gy;
        for (int i = threadIdx.x; i < HW * 4 / 128; i += T2)
            l2_prefetch(yb + i * 128);
    }

    cudaGridDependencySynchronize();

    const int ja = c_skel_a[l];
    const int jb = c_skel_b[l];
    if (threadIdx.x < Pn) {
        const float* pa = peaks + ((size_t)(b * Kdim + ja) * Pn + threadIdx.x) * 3;
        sax[threadIdx.x] = pa[0]; say[threadIdx.x] = pa[1]; sas[threadIdx.x] = pa[2];
    } else if (threadIdx.x >= 32 && threadIdx.x < 32 + Pn) {
        int j = threadIdx.x - 32;
        const float* pb = peaks + ((size_t)(b * Kdim + jb) * Pn + j) * 3;
        sbx[j] = pb[0]; sby[j] = pb[1]; sbs[j] = pb[2];
    }

    cp_wait<0>();
    __syncthreads();

    int   lin[2][Sn];
    float xp [2][Sn];
    float vyv[2];
    float halfs[2];
    bool  pv[2];
    const float step = 1.0f / 9.0f;

    #pragma unroll
    for (int q = 0; q < 2; ++q) {
        int pr = threadIdx.x + q * T2;
        bool act = (pr < Pn * Pn);
        int i = act ? (pr / Pn) : 0;
        int j = act ? (pr - i * Pn) : 0;
        float ax = sax[i], ay = say[i], sa = sas[i];
        float bx = sbx[j], by = sby[j], sb = sbs[j];
        bool valid = act && (sa > 0.1f) && (sb > 0.1f);
        pv[q] = valid;
        halfs[q] = 0.5f * (sa + sb);
        float dxl = bx - ax;
        float dyl = by - ay;
        float norm = sqrtf(__fadd_rn(__fmul_rn(dxl, dxl), __fmul_rn(dyl, dyl))) + 1e-8f;
        float vx = dxl / norm;
        float vy = dyl / norm;
        vyv[q] = vy;
        #pragma unroll
        for (int s = 0; s < Sn; ++s) {
            float t = (float)s * step;
            // no-FMA: a ulp flip at a .5 boundary changes the gathered cell
            float xs = __fadd_rn(ax, __fmul_rn(t, dxl));
            float ys = __fadd_rn(ay, __fmul_rn(t, dyl));
            float fx = fminf(fmaxf(rintf(xs), 0.0f), (float)(Wdim - 1));
            float fy = fminf(fmaxf(rintf(ys), 0.0f), (float)(Hdim - 1));
            int li = valid ? ((int)fy * Wdim + (int)fx) : 0;
            lin[q][s] = li;
            xp[q][s] = __fmul_rn(s2[li], vx);
        }
    }
    __syncthreads();                 // all pafx reads done; buffer free

    for (int i = threadIdx.x; i < NG; i += T2)
        cp16(&((float4*)s2)[i], &gy[i]);
    cp_commit();
    cp_wait<0>();
    __syncthreads();

    float* co = conn + (size_t)bl * Pn * Pn;
    #pragma unroll
    for (int q = 0; q < 2; ++q) {
        int pr = threadIdx.x + q * T2;
        bool act = (pr < Pn * Pn);
        float sum = 0.0f;
        int c = 0;
        #pragma unroll
        for (int s = 0; s < Sn; ++s) {
            float v = __fadd_rn(xp[q][s], __fmul_rn(s2[lin[q][s]], vyv[q]));
            sum = __fadd_rn(sum, v);
            c += (v > 0.05f) ? 1 : 0;
        }
        float outv = 0.0f;
        if (pv[q]) {
            float mean = sum / 10.0f;
            float ratio = (float)c / 10.0f;
            if (mean > 0.0f && ratio > 0.8f)
                outv = mean + halfs[q];
        }
        if (act) co[pr] = outv;
    }
}

// ---------------------------------------------------------------------------
extern "C" void kernel_launch(void* const* d_in, const int* in_sizes, int n_in,
                              void* d_out, int out_size)
{
    const float* heat = (const float*)d_in[0];
    const float* paf  = (const float*)d_in[1];
    float* out   = (float*)d_out;
    float* peaks = out;                                  // B*K*P*3 = 48960
    float* conn  = out + (size_t)Bdim * Kdim * Pn * 3;   // B*L*P*P = 547200

    const int smem2 = HW * 4;                            // 102400 -> 2 blocks/SM
    cudaFuncSetAttribute(stage2_kernel, cudaFuncAttributeMaxDynamicSharedMemorySize, smem2);

    stage1_kernel<<<NCH, T1>>>(heat, peaks);

    cudaLaunchConfig_t cfg = {};
    cfg.gridDim = dim3(Bdim * Ln);
    cfg.blockDim = dim3(T2);
    cfg.dynamicSmemBytes = smem2;
    cfg.stream = 0;
    cudaLaunchAttribute attrs[1];
    attrs[0].id = cudaLaunchAttributeProgrammaticStreamSerialization;
    attrs[0].val.programmaticStreamSerializationAllowed = 1;
    cfg.attrs = attrs;
    cfg.numAttrs = 1;
    cudaLaunchKernelEx(&cfg, stage2_kernel, paf, (const float*)peaks, conn);
}

// round 17
// speedup vs baseline: 1.4771x; 1.0468x over previous
#include <cuda_runtime.h>
#include <cstdint>

#define Bdim 32
#define Kdim 17
#define Hdim 160
#define Wdim 160
#define HW   (Hdim*Wdim)
#define NG   (HW/4)
#define Pn   30
#define Sn   10
#define Ln   19
#define NCH  (Bdim*Kdim)
#define T1   320
#define NSTRIP 20
#define SPX   8
#define RPB   10
#define CAP1  4096
#define T2   512
#define NBINS 1024
#define SCAP  128
#define NEGF  (-1.0e30f)

__constant__ int c_skel_a[Ln] = {15,13,16,14,11, 5, 6, 5, 5, 6, 7, 8, 1, 0, 0, 1, 2, 3, 4};
__constant__ int c_skel_b[Ln] = {13,11,14,12,12,11,12, 6, 7, 8, 9,10, 2, 1, 2, 3, 4, 5, 6};

// ---------------- cp.async helpers ----------------
__device__ __forceinline__ void cp16(void* s, const void* g) {
    unsigned sa = (unsigned)__cvta_generic_to_shared(s);
    asm volatile("cp.async.cg.shared.global [%0], [%1], 16;\n" :: "r"(sa), "l"(g));
}
__device__ __forceinline__ void cp_commit() { asm volatile("cp.async.commit_group;\n"); }
template <int N>
__device__ __forceinline__ void cp_wait() { asm volatile("cp.async.wait_group %0;\n" :: "n"(N)); }

// monotone bin: v = h^9 (uniform-izes max-of-9 peak-score distribution)
__device__ __forceinline__ int bin_of(float h) {
    float h2 = h * h;
    float h4 = h2 * h2;
    float v  = h4 * h4 * h;
    int b = (int)(v * (float)NBINS);
    return b < 0 ? 0 : (b > NBINS - 1 ? NBINS - 1 : b);
}

__device__ __forceinline__ float max3(float a, float b, float c) {
    return fmaxf(fmaxf(a, b), c);
}

// load one row of an 8px strip: 2 contiguous float4 + 2 edge scalars.
__device__ __forceinline__ void loadrow8(const float* __restrict__ hp,
                                         int y, int x0, bool lf, bool rt,
                                         float rm[8], float px[8])
{
    if (y < 0 || y >= Hdim) {
        #pragma unroll
        for (int j = 0; j < SPX; ++j) { rm[j] = NEGF; px[j] = NEGF; }
        return;
    }
    const float4* p4 = (const float4*)(hp + y * Wdim + x0);
    float4 A = __ldg(p4);
    float4 B = __ldg(p4 + 1);
    float w[SPX + 2];
    w[0] = lf ? __ldg(hp + y * Wdim + x0 - 1) : NEGF;
    w[1] = A.x; w[2] = A.y; w[3] = A.z; w[4] = A.w;
    w[5] = B.x; w[6] = B.y; w[7] = B.z; w[8] = B.w;
    w[9] = rt ? __ldg(hp + y * Wdim + x0 + SPX) : NEGF;
    #pragma unroll
    for (int j = 0; j < SPX; ++j) {
        px[j] = w[j + 1];
        rm[j] = max3(w[j], w[j + 1], w[j + 2]);
    }
}

// ---------------------------------------------------------------------------
// Stage 1: R10 detector + histogram cutoff, with the R14-proven register-
// resident top-30 select (4 keys/lane, butterfly max) replacing the LDS-scan
// argmax rounds.
// ---------------------------------------------------------------------------
__global__ void __launch_bounds__(T1) stage1_kernel(const float* __restrict__ heat,
                                                    float* __restrict__ out_peaks)
{
    if (threadIdx.x == 0) cudaTriggerProgrammaticLaunchCompletion();

    __shared__ unsigned long long list[CAP1];
    __shared__ unsigned hist[NBINS];
    __shared__ unsigned long long surv[SCAP];
    __shared__ unsigned long long s_top[Pn];
    __shared__ int s_cnt, s_sc, s_cut;

    const int ch = blockIdx.x;
    const float* hp = heat + (size_t)ch * HW;
    const int tid = threadIdx.x;
    const int lane = tid & 31;

    for (int i = tid; i < NBINS; i += T1) hist[i] = 0;
    if (tid == 0) { s_cnt = 0; s_sc = 0; s_cut = 0; }
    __syncthreads();

    // ---- pass 1: strip sweep (20 strips x 16 bands, 8px x 10row strips) ----
    const int strip = tid % NSTRIP;
    const int band  = tid / NSTRIP;
    const int x0 = strip * SPX;
    const int y0 = band * RPB;
    const bool lf = (strip > 0);
    const bool rt = (strip < NSTRIP - 1);

    float rmU[SPX], rmC[SPX], rmD[SPX];
    float C8[SPX], D8[SPX];

    loadrow8(hp, y0 - 1, x0, lf, rt, rmU, D8);
    loadrow8(hp, y0,     x0, lf, rt, rmC, C8);

    #pragma unroll 2
    for (int r = 0; r < RPB; ++r) {
        const int y = y0 + r;
        loadrow8(hp, y + 1, x0, lf, rt, rmD, D8);
        #pragma unroll
        for (int j = 0; j < SPX; ++j) {
            float h = C8[j];
            if (h > 0.1f && h >= rmU[j] && h >= rmC[j] && h >= rmD[j]) {
                int pos = atomicAdd(&s_cnt, 1);
                if (pos < CAP1) {
                    unsigned idx = (unsigned)(y * Wdim + x0 + j);
                    list[pos] = ((unsigned long long)__float_as_uint(h) << 32) |
                                (unsigned long long)(0xFFFFFFFFu - idx);
                }
            }
        }
        #pragma unroll
        for (int j = 0; j < SPX; ++j) {
            rmU[j] = rmC[j]; rmC[j] = rmD[j]; C8[j] = D8[j];
        }
    }
    __syncthreads();

    const int m = (s_cnt < CAP1) ? s_cnt : CAP1;

    // ---- histogram over the candidate list ----
    for (int i = tid; i < m; i += T1) {
        float h = __uint_as_float((unsigned)(list[i] >> 32));
        atomicAdd(&hist[bin_of(h)], 1u);
    }
    __syncthreads();

    // ---- warp 0: cutoff bin = highest bin whose suffix count >= Pn ----
    if (tid < 32) {
        int acc = 0, cut = 0;
        for (int base = NBINS - 32; base >= 0; base -= 32) {
            int s = (int)hist[base + lane];
            #pragma unroll
            for (int off = 1; off < 32; off <<= 1) {
                int t = __shfl_down_sync(0xffffffffu, s, off);
                if (lane + off < 32) s += t;
            }
            int chunk_total = __shfl_sync(0xffffffffu, s, 0);
            if (acc + chunk_total >= Pn) {
                unsigned msk = __ballot_sync(0xffffffffu, acc + s >= Pn);
                cut = base + (31 - __clz(msk));
                break;
            }
            acc += chunk_total;
        }
        if (lane == 0) s_cut = cut;
    }
    __syncthreads();

    // ---- compact survivors (bin >= cut) ----
    const int cut = s_cut;
    for (int i = tid; i < m; i += T1) {
        unsigned long long key = list[i];
        if (bin_of(__uint_as_float((unsigned)(key >> 32))) >= cut) {
            int pos = atomicAdd(&s_sc, 1);
            if (pos < SCAP) surv[pos] = key;
        }
    }
    __syncthreads();

    // ---- warp 0: register-resident top-30 (R14-proven) + subpixel refine ----
    if (tid < 32) {
        const int n = (s_sc < SCAP) ? s_sc : SCAP;
        unsigned long long v0 = (lane      < n) ? surv[lane]      : 0ull;
        unsigned long long v1 = (lane + 32 < n) ? surv[lane + 32] : 0ull;
        unsigned long long v2 = (lane + 64 < n) ? surv[lane + 64] : 0ull;
        unsigned long long v3 = (lane + 96 < n) ? surv[lane + 96] : 0ull;
        for (int p = 0; p < Pn; ++p) {
            unsigned long long m01 = v0 > v1 ? v0 : v1;
            unsigned long long m23 = v2 > v3 ? v2 : v3;
            unsigned long long mx = m01 > m23 ? m01 : m23;
            #pragma unroll
            for (int off = 16; off > 0; off >>= 1) {
                unsigned long long o = __shfl_xor_sync(0xffffffffu, mx, off);
                if (o > mx) mx = o;
            }
            if (lane == 0) s_top[p] = mx;
            if      (v0 == mx) v0 = 0ull;      // keys unique: one clear total
            else if (v1 == mx) v1 = 0ull;
            else if (v2 == mx) v2 = 0ull;
            else if (v3 == mx) v3 = 0ull;
        }
        __syncwarp();

        if (lane < Pn) {
            unsigned long long key = s_top[lane];
            float px = 0.f, py = 0.f, sc = 0.f;
            if (key != 0ull) {
                unsigned idx = 0xFFFFFFFFu - (unsigned)(key & 0xFFFFFFFFu);
                float h = __uint_as_float((unsigned)(key >> 32));
                int y = idx / Wdim;
                int x = idx - y * Wdim;
                float dx = 0.f, dy = 0.f;
                if (y > 0 && y < Hdim - 1 && x > 0 && x < Wdim - 1) {
                    float r = __ldg(hp + idx + 1),    l = __ldg(hp + idx - 1);
                    float d = __ldg(hp + idx + Wdim), u = __ldg(hp + idx - Wdim);
                    float dxr = 0.5f * (r - l);
                    float dxx = (r + l) - 2.0f * h;
                    dx = (fabsf(dxx) > 1e-6f) ? (dxr / (-dxx)) : dxr;
                    float dyr = 0.5f * (d - u);
                    float dyy = (d + u) - 2.0f * h;
                    dy = (fabsf(dyy) > 1e-6f) ? (dyr / (-dyy)) : dyr;
                }
                px = (float)x + dx;
                py = (float)y + dy;
                sc = h;
            }
            float* o = out_peaks + ((size_t)ch * Pn + lane) * 3;
            o[0] = px; o[1] = py; o[2] = sc;
        }
    }
}

// ---------------------------------------------------------------------------
// Stage 2 (R10, byte-identical): per-(b,l) limb, one PAF channel in smem at a
// time (100KB, 2 blocks/SM); PDL overlaps the PAF-x prologue with stage1.
// ---------------------------------------------------------------------------
__global__ void __launch_bounds__(T2, 2) stage2_kernel(const float* __restrict__ paf,
                                                       const float* __restrict__ peaks,
                                                       float* __restrict__ conn)
{
    extern __shared__ float s2[];                // HW floats (reused x then y)

    __shared__ float sax[Pn], say[Pn], sas[Pn];
    __shared__ float sbx[Pn], sby[Pn], sbs[Pn];

    const int bl = blockIdx.x;      // b*Ln + l
    const int b = bl / Ln;
    const int l = bl - b * Ln;

    const float4* gx = (const float4*)(paf + ((size_t)b * 38 + 2 * l) * HW);
    const float4* gy = (const float4*)(paf + ((size_t)b * 38 + 2 * l + 1) * HW);

    for (int i = threadIdx.x; i < NG; i += T2)
        cp16(&((float4*)s2)[i], &gx[i]);
    cp_commit();

    cudaGridDependencySynchronize();

    const int ja = c_skel_a[l];
    const int jb = c_skel_b[l];
    if (threadIdx.x < Pn) {
        const float* pa = peaks + ((size_t)(b * Kdim + ja) * Pn + threadIdx.x) * 3;
        sax[threadIdx.x] = pa[0]; say[threadIdx.x] = pa[1]; sas[threadIdx.x] = pa[2];
    } else if (threadIdx.x >= 32 && threadIdx.x < 32 + Pn) {
        int j = threadIdx.x - 32;
        const float* pb = peaks + ((size_t)(b * Kdim + jb) * Pn + j) * 3;
        sbx[j] = pb[0]; sby[j] = pb[1]; sbs[j] = pb[2];
    }

    cp_wait<0>();
    __syncthreads();

    int   lin[2][Sn];
    float xp [2][Sn];
    float vyv[2];
    float halfs[2];
    bool  pv[2];
    const float step = 1.0f / 9.0f;

    #pragma unroll
    for (int q = 0; q < 2; ++q) {
        int pr = threadIdx.x + q * T2;
        bool act = (pr < Pn * Pn);
        int i = act ? (pr / Pn) : 0;
        int j = act ? (pr - i * Pn) : 0;
        float ax = sax[i], ay = say[i], sa = sas[i];
        float bx = sbx[j], by = sby[j], sb = sbs[j];
        bool valid = act && (sa > 0.1f) && (sb > 0.1f);
        pv[q] = valid;
        halfs[q] = 0.5f * (sa + sb);
        float dxl = bx - ax;
        float dyl = by - ay;
        float norm = sqrtf(__fadd_rn(__fmul_rn(dxl, dxl), __fmul_rn(dyl, dyl))) + 1e-8f;
        float vx = dxl / norm;
        float vy = dyl / norm;
        vyv[q] = vy;
        #pragma unroll
        for (int s = 0; s < Sn; ++s) {
            float t = (float)s * step;
            // no-FMA: a ulp flip at a .5 boundary changes the gathered cell
            float xs = __fadd_rn(ax, __fmul_rn(t, dxl));
            float ys = __fadd_rn(ay, __fmul_rn(t, dyl));
            float fx = fminf(fmaxf(rintf(xs), 0.0f), (float)(Wdim - 1));
            float fy = fminf(fmaxf(rintf(ys), 0.0f), (float)(Hdim - 1));
            int li = valid ? ((int)fy * Wdim + (int)fx) : 0;
            lin[q][s] = li;
            xp[q][s] = __fmul_rn(s2[li], vx);
        }
    }
    __syncthreads();                 // all pafx reads done; buffer free

    for (int i = threadIdx.x; i < NG; i += T2)
        cp16(&((float4*)s2)[i], &gy[i]);
    cp_commit();
    cp_wait<0>();
    __syncthreads();

    float* co = conn + (size_t)bl * Pn * Pn;
    #pragma unroll
    for (int q = 0; q < 2; ++q) {
        int pr = threadIdx.x + q * T2;
        bool act = (pr < Pn * Pn);
        float sum = 0.0f;
        int c = 0;
        #pragma unroll
        for (int s = 0; s < Sn; ++s) {
            float v = __fadd_rn(xp[q][s], __fmul_rn(s2[lin[q][s]], vyv[q]));
            sum = __fadd_rn(sum, v);
            c += (v > 0.05f) ? 1 : 0;
        }
        float outv = 0.0f;
        if (pv[q]) {
            float mean = sum / 10.0f;
            float ratio = (float)c / 10.0f;
            if (mean > 0.0f && ratio > 0.8f)
                outv = mean + halfs[q];
        }
        if (act) co[pr] = outv;
    }
}

// ---------------------------------------------------------------------------
extern "C" void kernel_launch(void* const* d_in, const int* in_sizes, int n_in,
                              void* d_out, int out_size)
{
    const float* heat = (const float*)d_in[0];
    const float* paf  = (const float*)d_in[1];
    float* out   = (float*)d_out;
    float* peaks = out;                                  // B*K*P*3 = 48960
    float* conn  = out + (size_t)Bdim * Kdim * Pn * 3;   // B*L*P*P = 547200

    const int smem2 = HW * 4;                            // 102400 -> 2 blocks/SM
    cudaFuncSetAttribute(stage2_kernel, cudaFuncAttributeMaxDynamicSharedMemorySize, smem2);

    stage1_kernel<<<NCH, T1>>>(heat, peaks);

    cudaLaunchConfig_t cfg = {};
    cfg.gridDim = dim3(Bdim * Ln);
    cfg.blockDim = dim3(T2);
    cfg.dynamicSmemBytes = smem2;
    cfg.stream = 0;
    cudaLaunchAttribute attrs[1];
    attrs[0].id = cudaLaunchAttributeProgrammaticStreamSerialization;
    attrs[0].val.programmaticStreamSerializationAllowed = 1;
    cfg.attrs = attrs;
    cfg.numAttrs = 1;
    cudaLaunchKernelEx(&cfg, stage2_kernel, paf, (const float*)peaks, conn);
}